// round 10
// baseline (speedup 1.0000x reference)
#include <cuda_runtime.h>

#define N_  25000
#define E_  400000
#define U_  48
#define D_  12
#define RP  258   // k_fuse transposed tile pitch (256 rows + 2 pad)
#define RPN 66    // k_node transposed tile pitch (64 rows + 2 pad)

typedef unsigned long long u64;

__device__ float g_h   [N_*U_];
__device__ float g_h2  [N_*U_];
__device__ float g_h3  [N_*U_];
__device__ float g_h4  [N_*U_];
__device__ float g_preh[N_*U_];
__device__ float g_w   [E_*U_];
__device__ float g_prew[E_*U_];
__device__ float g_stat[2][192];   // [parity][node sum|sumsq, edge sum|sumsq]
__device__ float g_zsum;

__device__ __forceinline__ float siluf(float v){ return __fdividef(v, 1.0f + __expf(-v)); }
__device__ __forceinline__ float sigm(float v){ return __fdividef(1.0f, 1.0f + __expf(-v)); }
__device__ __forceinline__ u64 pk2(float x, float y){
    u64 r; asm("mov.b64 %0,{%1,%2};" : "=l"(r) : "f"(x), "f"(y)); return r;
}
__device__ __forceinline__ void fma2(u64& d, u64 a, u64 b){
    asm("fma.rn.f32x2 %0,%1,%2,%0;" : "+l"(d) : "l"(a), "l"(b));
}
__device__ __forceinline__ float2 up2(u64 v){
    float2 f; asm("mov.b64 {%0,%1},%2;" : "=f"(f.x), "=f"(f.y) : "l"(v)); return f;
}

// row-major 48-vec x 24-col slice (used by k_head only)
__device__ __forceinline__ void mm24(const float* in, const float* Wc, u64* acc){
    #pragma unroll 4
    for (int k = 0; k < U_; k++){
        float a = in[k];
        u64 pa = pk2(a, a);
        const float4* w4 = reinterpret_cast<const float4*>(Wc + k*U_);
        #pragma unroll
        for (int q = 0; q < 6; q++){
            float4 wv = w4[q];
            fma2(acc[2*q],   pa, pk2(wv.x, wv.y));
            fma2(acc[2*q+1], pa, pk2(wv.z, wv.w));
        }
    }
}

__global__ void k_init(const float* __restrict__ x, const float* __restrict__ ea,
                       const float* __restrict__ W0, const float* __restrict__ b0,
                       const float* __restrict__ eW0, const float* __restrict__ eb0){
    int total = N_*U_ + E_*U_;
    for (int idx = blockIdx.x*blockDim.x + threadIdx.x; idx < total; idx += gridDim.x*blockDim.x){
        if (idx < N_*U_){
            int r = idx / U_, c = idx - r*U_;
            g_h[idx] = siluf(fmaf(x[2*r], W0[2*c], fmaf(x[2*r+1], W0[2*c+1], b0[c])));
        } else {
            int j = idx - N_*U_;
            int r = j / U_, c = j - r*U_;
            g_w[j] = siluf(fmaf(ea[r], eW0[c], eb0[c]));
        }
    }
    if (blockIdx.x == 0 && threadIdx.x == 0) g_zsum = 0.0f;
}

// ---------- node projections: preh(h1), h2, h3, h4 (+ fold prev h update, + norm calc) ----------
__global__ void __launch_bounds__(512, 2)
k_node(int layer, int first,
       const float* __restrict__ W1, const float* __restrict__ W2,
       const float* __restrict__ W3, const float* __restrict__ W4,
       const float* __restrict__ b1, const float* __restrict__ b2,
       const float* __restrict__ b3, const float* __restrict__ b4,
       const float* __restrict__ vg, const float* __restrict__ vb){
    extern __shared__ float sm[];
    float* hT  = sm;                    // 48*66 = 3168
    float* Wt  = hT + 48*RPN;           // 9216
    float* bs  = Wt + 4*U_*U_;          // 192
    float* nrm = bs + 192;              // 96
    int tid = threadIdx.x;
    int row0 = blockIdx.x * 64;
    int nrows = min(64, N_ - row0);
    int prev = (layer + 1) & 1, cur = layer & 1;

    if (!first && tid < U_){
        float m  = g_stat[prev][tid] * (1.0f/N_);
        float va = fmaxf(g_stat[prev][U_+tid]*(1.0f/N_) - m*m, 0.0f);
        float sc = vg[(layer-1)*U_ + tid] * rsqrtf(va + 1e-5f);
        nrm[tid] = sc;
        nrm[U_+tid] = vb[(layer-1)*U_ + tid] - m*sc;
    }
    if (blockIdx.x == 0 && tid < 192) g_stat[cur][tid] = 0.0f;
    for (int idx = tid; idx < 4*U_*U_; idx += 512){
        int m = idx / (U_*U_), j = idx - m*(U_*U_);
        int c = j / U_, k = j - c*U_;
        const float* src = (m==0) ? W1 : (m==1) ? W2 : (m==2) ? W3 : W4;
        Wt[m*(U_*U_) + k*U_ + c] = src[layer*U_*U_ + j];
    }
    if (tid < 4*U_){
        int m = tid / U_, c = tid - m*U_;
        const float* src = (m==0) ? b1 : (m==1) ? b2 : (m==2) ? b3 : b4;
        bs[tid] = src[layer*U_ + c];
    }
    __syncthreads();

    {   // P0: update h, stage transposed
        const float4* hsrc = reinterpret_cast<const float4*>(g_h + row0*U_);
        const float4* psrc = reinterpret_cast<const float4*>(g_preh + row0*U_);
        float4* hdst = reinterpret_cast<float4*>(g_h + row0*U_);
        int cnt = nrows*12;
        for (int idx = tid; idx < cnt; idx += 512){
            float4 v = hsrc[idx];
            int r = idx / 12, c4 = (idx - r*12) * 4;
            if (!first){
                float4 p = psrc[idx];
                v.x += siluf(fmaf(p.x, nrm[c4],   nrm[48+c4]));
                v.y += siluf(fmaf(p.y, nrm[c4+1], nrm[48+c4+1]));
                v.z += siluf(fmaf(p.z, nrm[c4+2], nrm[48+c4+2]));
                v.w += siluf(fmaf(p.w, nrm[c4+3], nrm[48+c4+3]));
                hdst[idx] = v;
            }
            hT[(c4+0)*RPN + r] = v.x;
            hT[(c4+1)*RPN + r] = v.y;
            hT[(c4+2)*RPN + r] = v.z;
            hT[(c4+3)*RPN + r] = v.w;
        }
    }
    __syncthreads();

    // GEMM: thread = (matrix m, row-pair rp, col-group cg); 2 rows x 12 cols
    int m  = tid >> 7;
    int s  = tid & 127;
    int rp = s & 31;
    int cg = s >> 5;
    int r0 = 2*rp;
    if (r0 < nrows){
        u64 aA[6], aB[6];
        #pragma unroll
        for (int q = 0; q < 6; q++){ aA[q] = 0ull; aB[q] = 0ull; }
        const float* Wm = Wt + m*(U_*U_) + cg*12;
        #pragma unroll 4
        for (int k = 0; k < U_; k++){
            float2 in2 = *reinterpret_cast<const float2*>(hT + k*RPN + r0);
            u64 pa0 = pk2(in2.x, in2.x);
            u64 pa1 = pk2(in2.y, in2.y);
            const float4* w4 = reinterpret_cast<const float4*>(Wm + k*U_);
            #pragma unroll
            for (int q = 0; q < 3; q++){
                float4 wv = w4[q];
                u64 w0 = pk2(wv.x, wv.y), w1 = pk2(wv.z, wv.w);
                fma2(aA[2*q],   pa0, w0); fma2(aA[2*q+1], pa0, w1);
                fma2(aB[2*q],   pa1, w0); fma2(aB[2*q+1], pa1, w1);
            }
        }
        float* base = (m==0) ? g_preh : (m==1) ? g_h2 : (m==2) ? g_h3 : g_h4;
        const float* bp = bs + m*U_ + cg*12;
        float4* d0 = reinterpret_cast<float4*>(base + (row0 + r0)*U_ + cg*12);
        #pragma unroll
        for (int q = 0; q < 3; q++){
            float2 f0 = up2(aA[2*q]), f1 = up2(aA[2*q+1]);
            float4 o; o.x = f0.x + bp[4*q]; o.y = f0.y + bp[4*q+1];
            o.z = f1.x + bp[4*q+2]; o.w = f1.y + bp[4*q+3];
            d0[q] = o;
        }
        if (r0 + 1 < nrows){
            float4* d1 = reinterpret_cast<float4*>(base + (row0 + r0 + 1)*U_ + cg*12);
            #pragma unroll
            for (int q = 0; q < 3; q++){
                float2 f0 = up2(aB[2*q]), f1 = up2(aB[2*q+1]);
                float4 o; o.x = f0.x + bp[4*q]; o.y = f0.y + bp[4*q+1];
                o.z = f1.x + bp[4*q+2]; o.w = f1.y + bp[4*q+3];
                d1[q] = o;
            }
        }
    }
}

// ---------- fused: w update + gated agg + edge matmul + BN stats (+ norm calc) ----------
__global__ void __launch_bounds__(512, 2)
k_fuse(int layer, int first, const float* __restrict__ eW, const float* __restrict__ eb,
       const int* __restrict__ dst,
       const float* __restrict__ eg, const float* __restrict__ ebv){
    extern __shared__ float sm[];
    float* wT   = sm;                   // 48*258 = 12384
    float* Wt   = wT + 48*RP;           // 2304
    float* h3s  = Wt + U_*U_;           // 768
    float* aggs = h3s + 16*U_;          // 768
    float* ebs  = aggs + 16*U_;         // 48
    float* nrm  = ebs + U_;             // 96
    float* pst  = nrm + 96;             // 96
    float* wst  = pst + 96;             // 96
    int*   dsti = (int*)(wst + 96);     // 256
    int tid = threadIdx.x;
    int node0 = blockIdx.x * 16;
    int nn = min(16, N_ - node0);
    int ne = nn * 16;
    int e0 = node0 * 16;
    int prev = (layer + 1) & 1, cur = layer & 1;

    if (!first && tid < U_){
        float mw = g_stat[prev][96+tid] * (1.0f/E_);
        float vw = fmaxf(g_stat[prev][144+tid]*(1.0f/E_) - mw*mw, 0.0f);
        float sw = eg[(layer-1)*U_ + tid] * rsqrtf(vw + 1e-5f);
        nrm[tid] = sw;
        nrm[U_+tid] = ebv[(layer-1)*U_ + tid] - mw*sw;
    }
    if (tid < 96) pst[tid] = 0.0f;
    else if (tid < 192) wst[tid - 96] = 0.0f;
    for (int idx = tid; idx < U_*U_; idx += 512){
        int c = idx / U_, k = idx - c*U_;
        Wt[k*U_ + c] = eW[layer*U_*U_ + idx];
    }
    for (int idx = tid; idx < nn*U_; idx += 512) h3s[idx] = g_h3[node0*U_ + idx];
    if (tid < U_) ebs[tid] = eb[layer*U_ + tid];
    if (tid < ne) dsti[tid] = dst[e0 + tid];
    __syncthreads();

    {   // P0: update w, stage transposed
        const float4* wsrc = reinterpret_cast<const float4*>(g_w + e0*U_);
        const float4* psrc = reinterpret_cast<const float4*>(g_prew + e0*U_);
        float4* wdst = reinterpret_cast<float4*>(g_w + e0*U_);
        int cnt = ne*12;
        for (int idx = tid; idx < cnt; idx += 512){
            float4 v = wsrc[idx];
            int r = idx / 12, c4 = (idx - r*12) * 4;
            if (!first){
                float4 p = psrc[idx];
                v.x += siluf(fmaf(p.x, nrm[c4],   nrm[48+c4]));
                v.y += siluf(fmaf(p.y, nrm[c4+1], nrm[48+c4+1]));
                v.z += siluf(fmaf(p.z, nrm[c4+2], nrm[48+c4+2]));
                v.w += siluf(fmaf(p.w, nrm[c4+3], nrm[48+c4+3]));
                wdst[idx] = v;
            }
            wT[(c4+0)*RP + r] = v.x;
            wT[(c4+1)*RP + r] = v.y;
            wT[(c4+2)*RP + r] = v.z;
            wT[(c4+3)*RP + r] = v.w;
        }
    }
    __syncthreads();

    // P1: gated message + 16-edge butterfly -> aggs (warp per node)
    {
        int wid = tid >> 5, lane = tid & 31, j = lane >> 1, half = lane & 1;
        if (wid < nn){
            int row = wid*16 + j;
            int d = dsti[row];
            const float4* h2r = reinterpret_cast<const float4*>(g_h2 + d*U_) + half*6;
            const float* wc = wT + (half*24)*RP + row;
            float4 m[6];
            #pragma unroll
            for (int q = 0; q < 6; q++){
                float4 h = h2r[q];
                m[q].x = h.x * sigm(wc[(4*q+0)*RP]);
                m[q].y = h.y * sigm(wc[(4*q+1)*RP]);
                m[q].z = h.z * sigm(wc[(4*q+2)*RP]);
                m[q].w = h.w * sigm(wc[(4*q+3)*RP]);
            }
            #pragma unroll
            for (int o = 2; o <= 16; o <<= 1){
                #pragma unroll
                for (int q = 0; q < 6; q++){
                    m[q].x += __shfl_xor_sync(0xffffffffu, m[q].x, o);
                    m[q].y += __shfl_xor_sync(0xffffffffu, m[q].y, o);
                    m[q].z += __shfl_xor_sync(0xffffffffu, m[q].z, o);
                    m[q].w += __shfl_xor_sync(0xffffffffu, m[q].w, o);
                }
            }
            if (j == 0){
                float4* ag = reinterpret_cast<float4*>(aggs + wid*U_ + half*24);
                #pragma unroll
                for (int q = 0; q < 6; q++) ag[q] = m[q];
            }
        }
    }
    __syncthreads();

    // P2a: GEMM, 2 rows x 12 cols per thread
    int rp = tid & 127;
    int cg = tid >> 7;
    int r0 = 2*rp;
    u64 aA[6], aB[6];
    #pragma unroll
    for (int q = 0; q < 6; q++){ aA[q] = 0ull; aB[q] = 0ull; }
    if (r0 < ne){
        const float* Wm = Wt + cg*12;
        #pragma unroll 4
        for (int k = 0; k < U_; k++){
            float2 in2 = *reinterpret_cast<const float2*>(wT + k*RP + r0);
            u64 pa0 = pk2(in2.x, in2.x);
            u64 pa1 = pk2(in2.y, in2.y);
            const float4* w4 = reinterpret_cast<const float4*>(Wm + k*U_);
            #pragma unroll
            for (int q = 0; q < 3; q++){
                float4 wv = w4[q];
                u64 w0 = pk2(wv.x, wv.y), w1 = pk2(wv.z, wv.w);
                fma2(aA[2*q],   pa0, w0); fma2(aA[2*q+1], pa0, w1);
                fma2(aB[2*q],   pa1, w0); fma2(aB[2*q+1], pa1, w1);
            }
        }
    }
    __syncthreads();   // all wT reads done before stash overwrites

    // P2b: epilogue + gmem write + stash prew into wT
    if (r0 < ne){
        const float* bp = ebs + cg*12;
        #pragma unroll
        for (int rr = 0; rr < 2; rr++){
            int row = r0 + rr;
            int e = e0 + row;
            int d = dsti[row];
            int node = row >> 4;
            const float4* h4r = reinterpret_cast<const float4*>(g_h4 + d*U_ + cg*12);
            const float4* h3r = reinterpret_cast<const float4*>(h3s + node*U_ + cg*12);
            float4* op = reinterpret_cast<float4*>(g_prew + e*U_ + cg*12);
            const u64* ac = (rr == 0) ? aA : aB;
            #pragma unroll
            for (int q = 0; q < 3; q++){
                float2 f0 = up2(ac[2*q]), f1 = up2(ac[2*q+1]);
                float4 a4 = h4r[q], a3 = h3r[q];
                float4 o;
                o.x = f0.x + bp[4*q+0] + a3.x + a4.x;
                o.y = f0.y + bp[4*q+1] + a3.y + a4.y;
                o.z = f1.x + bp[4*q+2] + a3.z + a4.z;
                o.w = f1.y + bp[4*q+3] + a3.w + a4.w;
                op[q] = o;
                wT[(cg*12 + 4*q+0)*RP + row] = o.x;
                wT[(cg*12 + 4*q+1)*RP + row] = o.y;
                wT[(cg*12 + 4*q+2)*RP + row] = o.z;
                wT[(cg*12 + 4*q+3)*RP + row] = o.w;
            }
        }
    }
    __syncthreads();

    // P3: preh = h1 + agg/16 with node stats; edge stats over stashed prew
    for (int idx = tid; idx < nn*U_; idx += 512){
        int c = idx % U_;
        float v = g_preh[node0*U_ + idx] + aggs[idx] * 0.0625f;
        g_preh[node0*U_ + idx] = v;
        atomicAdd(&pst[c], v);
        atomicAdd(&pst[48+c], v*v);
    }
    if (tid < 192){
        int c = tid % U_, seg = tid / U_;
        int rend = min(seg*64 + 64, ne);
        float s = 0.0f, s2 = 0.0f;
        const float* col = wT + c*RP;
        for (int r2 = seg*64; r2 < rend; r2++){
            float v = col[r2];
            s += v; s2 += v*v;
        }
        atomicAdd(&wst[c], s);
        atomicAdd(&wst[48+c], s2);
    }
    __syncthreads();
    if (tid < 96) atomicAdd(&g_stat[cur][tid], pst[tid]);
    else if (tid < 192) atomicAdd(&g_stat[cur][tid], wst[tid - 96]);
}

// ---------- head ----------
__global__ void __launch_bounds__(512)
k_head(const float* __restrict__ pW0, const float* __restrict__ pb0,
       const float* __restrict__ pW1, const float* __restrict__ pb1,
       const float* __restrict__ pW2, const float* __restrict__ pb2,
       const float* __restrict__ zW0, const float* __restrict__ zb0,
       const float* __restrict__ zW1,
       const float* __restrict__ eg, const float* __restrict__ ebv,
       float* __restrict__ out){
    extern __shared__ float sm[];
    float* w_s = sm;                    // 256*49 = 12544
    float* W0t = w_s + 256*49;          // 2304
    float* W1t = W0t + U_*U_;           // 2304
    float* Zt  = W1t + U_*U_;           // 2304
    float* vec = Zt + U_*U_;            // 240
    float* nrm = vec + 240;             // 96
    float* zred = nrm + 96;             // 16
    int tid = threadIdx.x;
    int wid = tid >> 5, lane = tid & 31;
    int j = lane >> 1, half = lane & 1;
    int node0 = blockIdx.x * 16;
    int nn = min(16, N_ - node0);
    int ne = nn * 16;
    int e0 = node0 * 16;

    if (tid < U_){
        float mw = g_stat[(D_+1)&1][96+tid] * (1.0f/E_);
        float vw = fmaxf(g_stat[(D_+1)&1][144+tid]*(1.0f/E_) - mw*mw, 0.0f);
        float sw = eg[(D_-1)*U_ + tid] * rsqrtf(vw + 1e-5f);
        nrm[tid] = sw;
        nrm[U_+tid] = ebv[(D_-1)*U_ + tid] - mw*sw;
    }
    for (int idx = tid; idx < 3*U_*U_; idx += 512){
        int m = idx / (U_*U_), jj = idx - m*(U_*U_);
        int c = jj / U_, k = jj - c*U_;
        const float* src = (m==0) ? pW0 : (m==1) ? pW1 : zW0;
        float* dw = (m==0) ? W0t : (m==1) ? W1t : Zt;
        dw[k*U_ + c] = src[jj];
    }
    if (tid < 240){
        int m = tid / U_, c = tid - m*U_;
        const float* src = (m==0) ? pb0 : (m==1) ? pb1 : (m==2) ? pW2 : (m==3) ? zb0 : zW1;
        vec[tid] = src[c];
    }
    __syncthreads();

    {
        const float4* wsrc = reinterpret_cast<const float4*>(g_w + e0*U_);
        const float4* psrc = reinterpret_cast<const float4*>(g_prew + e0*U_);
        int cnt = ne*12;
        for (int idx = tid; idx < cnt; idx += 512){
            float4 v = wsrc[idx];
            float4 p = psrc[idx];
            int r = idx / 12, c4 = (idx - r*12) * 4;
            v.x += siluf(fmaf(p.x, nrm[c4],   nrm[48+c4]));
            v.y += siluf(fmaf(p.y, nrm[c4+1], nrm[48+c4+1]));
            v.z += siluf(fmaf(p.z, nrm[c4+2], nrm[48+c4+2]));
            v.w += siluf(fmaf(p.w, nrm[c4+3], nrm[48+c4+3]));
            float* wp = w_s + r*49 + c4;
            wp[0]=v.x; wp[1]=v.y; wp[2]=v.z; wp[3]=v.w;
        }
    }
    __syncthreads();

    int row = wid*16 + j;
    int e = e0 + row;

    if (wid < nn){
        const float* in = w_s + row*49;
        u64 acc[12];
        #pragma unroll
        for (int q = 0; q < 12; q++) acc[q] = 0ull;
        mm24(in, W0t + half*24, acc);
        float p[24];
        #pragma unroll
        for (int q = 0; q < 6; q++){
            float2 f0 = up2(acc[2*q]);
            float2 f1 = up2(acc[2*q+1]);
            p[4*q+0] = siluf(f0.x + vec[half*24 + 4*q+0]);
            p[4*q+1] = siluf(f0.y + vec[half*24 + 4*q+1]);
            p[4*q+2] = siluf(f1.x + vec[half*24 + 4*q+2]);
            p[4*q+3] = siluf(f1.y + vec[half*24 + 4*q+3]);
        }
        #pragma unroll
        for (int q = 0; q < 12; q++) acc[q] = 0ull;
        #pragma unroll
        for (int k = 0; k < U_; k++){
            float t = p[k % 24];
            float sh = __shfl_xor_sync(0xffffffffu, t, 1);
            float a = (((k >= 24) ? 1 : 0) == half) ? t : sh;
            u64 pa = pk2(a, a);
            const float4* w4 = reinterpret_cast<const float4*>(W1t + half*24 + k*U_);
            #pragma unroll
            for (int q = 0; q < 6; q++){
                float4 wv = w4[q];
                fma2(acc[2*q],   pa, pk2(wv.x, wv.y));
                fma2(acc[2*q+1], pa, pk2(wv.z, wv.w));
            }
        }
        float sp = 0.0f;
        #pragma unroll
        for (int q = 0; q < 6; q++){
            float2 f0 = up2(acc[2*q]);
            float2 f1 = up2(acc[2*q+1]);
            sp += siluf(f0.x + vec[48+half*24+4*q+0]) * vec[96+half*24+4*q+0];
            sp += siluf(f0.y + vec[48+half*24+4*q+1]) * vec[96+half*24+4*q+1];
            sp += siluf(f1.x + vec[48+half*24+4*q+2]) * vec[96+half*24+4*q+2];
            sp += siluf(f1.y + vec[48+half*24+4*q+3]) * vec[96+half*24+4*q+3];
        }
        sp += __shfl_xor_sync(0xffffffffu, sp, 1);
        float sv = sp + __ldg(pb2);

        #pragma unroll
        for (int q = 0; q < 12; q++) acc[q] = 0ull;
        mm24(in, Zt + half*24, acc);
        float zp = 0.0f;
        #pragma unroll
        for (int q = 0; q < 6; q++){
            float2 f0 = up2(acc[2*q]);
            float2 f1 = up2(acc[2*q+1]);
            zp += fmaxf(f0.x + vec[144+half*24+4*q+0], 0.0f) * vec[192+half*24+4*q+0];
            zp += fmaxf(f0.y + vec[144+half*24+4*q+1], 0.0f) * vec[192+half*24+4*q+1];
            zp += fmaxf(f1.x + vec[144+half*24+4*q+2], 0.0f) * vec[192+half*24+4*q+2];
            zp += fmaxf(f1.y + vec[144+half*24+4*q+3], 0.0f) * vec[192+half*24+4*q+3];
        }

        float mx = sv;
        #pragma unroll
        for (int o = 2; o <= 16; o <<= 1) mx = fmaxf(mx, __shfl_xor_sync(0xffffffffu, mx, o));
        float ex = __expf(sv - mx);
        float se = ex;
        #pragma unroll
        for (int o = 2; o <= 16; o <<= 1) se += __shfl_xor_sync(0xffffffffu, se, o);
        if (half == 0) out[e] = ex * __fdividef(1.0f, se);

        float zw = zp;
        #pragma unroll
        for (int o = 1; o <= 16; o <<= 1) zw += __shfl_xor_sync(0xffffffffu, zw, o);
        if (lane == 0) zred[wid] = zw;
    }
    if (wid >= nn && lane == 0) zred[wid] = 0.0f;
    __syncthreads();
    if (tid == 0){
        float t = 0.0f;
        #pragma unroll
        for (int i = 0; i < 16; i++) t += zred[i];
        atomicAdd(&g_zsum, t);
    }
}

__global__ void k_fin(const float* __restrict__ zb1, float* __restrict__ out){
    out[E_] = g_zsum * (1.0f/E_) + zb1[0];
}

extern "C" void kernel_launch(void* const* d_in, const int* in_sizes, int n_in,
                              void* d_out, int out_size){
    const float* x    = (const float*)d_in[0];
    const float* ea   = (const float*)d_in[1];
    const int*   ei   = (const int*)d_in[2];
    const int*   dst  = ei + E_;
    const float* vl0W = (const float*)d_in[3];
    const float* vl0b = (const float*)d_in[4];
    const float *vW[4], *vb[4];
    if (in_sizes[6] == D_*U_){
        for (int i = 0; i < 4; i++){ vW[i] = (const float*)d_in[5+2*i]; vb[i] = (const float*)d_in[6+2*i]; }
    } else {
        for (int i = 0; i < 4; i++){ vW[i] = (const float*)d_in[5+i]; vb[i] = (const float*)d_in[9+i]; }
    }
    const float* vbn_g = (const float*)d_in[13];
    const float* vbn_b = (const float*)d_in[14];
    const float* el0W  = (const float*)d_in[15];
    const float* el0b  = (const float*)d_in[16];
    const float* eW    = (const float*)d_in[17];
    const float* eb    = (const float*)d_in[18];
    const float* ebn_g = (const float*)d_in[19];
    const float* ebn_b = (const float*)d_in[20];
    const float* pW0   = (const float*)d_in[21];
    const float* pb0   = (const float*)d_in[22];
    const float* pW1   = (const float*)d_in[23];
    const float* pb1   = (const float*)d_in[24];
    const float* pW2   = (const float*)d_in[25];
    const float* pb2   = (const float*)d_in[26];
    const float* zW0   = (const float*)d_in[27];
    const float* zb0   = (const float*)d_in[28];
    const float* zW1   = (const float*)d_in[29];
    const float* zb1   = (const float*)d_in[30];
    float* out = (float*)d_out;

    const int smNode = (48*RPN + 4*U_*U_ + 192 + 96) * 4;
    const int smFuse = (48*RP + U_*U_ + 16*U_ + 16*U_ + U_ + 96 + 96 + 96 + 256) * 4;
    const int smHead = (256*49 + 3*U_*U_ + 240 + 96 + 16) * 4;
    cudaFuncSetAttribute(k_node, cudaFuncAttributeMaxDynamicSharedMemorySize, smNode);
    cudaFuncSetAttribute(k_fuse, cudaFuncAttributeMaxDynamicSharedMemorySize, smFuse);
    cudaFuncSetAttribute(k_head, cudaFuncAttributeMaxDynamicSharedMemorySize, smHead);

    const int gNode = (N_ + 63) / 64;     // 391
    const int gTile = (N_ + 15) / 16;     // 1563

    k_init<<<2048, 256>>>(x, ea, vl0W, vl0b, el0W, el0b);
    for (int L = 0; L < D_; L++){
        int first = (L == 0);
        k_node<<<gNode, 512, smNode>>>(L, first, vW[0], vW[1], vW[2], vW[3],
                                       vb[0], vb[1], vb[2], vb[3], vbn_g, vbn_b);
        k_fuse<<<gTile, 512, smFuse>>>(L, first, eW, eb, dst, ebn_g, ebn_b);
    }
    k_head<<<gTile, 512, smHead>>>(pW0, pb0, pW1, pb1, pW2, pb2, zW0, zb0, zW1,
                                   ebn_g, ebn_b, out);
    k_fin<<<1, 1>>>(zb1, out);
}